// round 6
// baseline (speedup 1.0000x reference)
#include <cuda_runtime.h>
#include <cuda_fp16.h>
#include <cstdint>

#define NV 10000
#define NC 100000
#define B  256
#define NGROUPS (NC / 4)           // 25000, exact
#define GRID_MAIN 1776             // 148 SMs * 12 blocks

// Dual table: row 2v = x, row 2v+1 = 1-x, each row 128 half2 (256 batch).
// 2*10000*128 half2 = 10.24 MB, L2-resident. Both entries rounded from fp32,
// so every literal value has rel err <= 2^-11 regardless of negation.
__device__ __half2 g_tab[2 * NV * (B / 2)];
// Per literal: precomputed half2-offset of its table row: (2v+neg)*128. 1.2 MB.
__device__ unsigned int g_off[NC * 3];
__device__ int g_is64;

// Detect dtype of lit_idx via odd 32-bit words (int64 high words are all 0).
__global__ void detect_k(const unsigned int* __restrict__ lit_idx_raw) {
    unsigned int acc = 0;
    for (int i = 0; i < 128; ++i) acc |= lit_idx_raw[2 * i + 1];
    g_is64 = (acc == 0) ? 1 : 0;
}

__global__ void pack_k(const unsigned int* __restrict__ idx_raw,
                       const unsigned int* __restrict__ neg_raw) {
    int i = blockIdx.x * blockDim.x + threadIdx.x;
    if (i < NC * 3) {
        int stride = g_is64 ? 2 : 1;
        unsigned int v = idx_raw[i * stride];
        unsigned int n = neg_raw[i * stride] & 1u;
        if (v >= NV) v = NV - 1;              // defensive clamp: no OOB ever
        g_off[i] = v * 256u + n * 128u;       // (2v+neg) * 128 half2 per row
    }
}

// Build fp16 dual table from fp32 input. 1-x computed in fp32 (exact for
// x in [0,1) up to fp32 eps), then rounded once to fp16.
__global__ void build_k(const float* __restrict__ input) {
    int i = blockIdx.x * blockDim.x + threadIdx.x;   // over NV*128 pair-slots
    if (i < NV * (B / 2)) {
        int v = i / (B / 2);
        int j = i % (B / 2);
        float2 x = ((const float2*)input)[i];
        g_tab[v * 256 + j]       = __floats2half2_rn(x.x, x.y);
        g_tab[v * 256 + 128 + j] = __floats2half2_rn(1.0f - x.x, 1.0f - x.y);
    }
}

__global__ void init_k(unsigned int* __restrict__ out) {
    out[threadIdx.x] = 0x7F800000u;   // +inf
}

// 128 threads/block, 12 blocks/SM. Thread t owns batch elems 2t,2t+1 (one
// half2 per gather -> warp reads one 128B line). Grid-stride over 4-clause
// groups: 3x uint4 index loads + 12 LDG.32 gathers in flight, then pure
// hmax2/hmin2 (exact selects, no extra rounding).
__global__ void __launch_bounds__(128, 12)
cnf_k(unsigned int* __restrict__ out) {
    const int t = threadIdx.x;
    __half2 m = __halves2half2(__ushort_as_half(0x7C00), __ushort_as_half(0x7C00)); // +inf

    for (int g = blockIdx.x; g < NGROUPS; g += GRID_MAIN) {
        const uint4* q = (const uint4*)(g_off + g * 12);   // 48B-aligned
        uint4 qa = __ldg(&q[0]);
        uint4 qb = __ldg(&q[1]);
        uint4 qc = __ldg(&q[2]);

        __half2 x0  = __ldg(&g_tab[qa.x + t]);
        __half2 x1  = __ldg(&g_tab[qa.y + t]);
        __half2 x2  = __ldg(&g_tab[qa.z + t]);
        __half2 x3  = __ldg(&g_tab[qa.w + t]);
        __half2 x4  = __ldg(&g_tab[qb.x + t]);
        __half2 x5  = __ldg(&g_tab[qb.y + t]);
        __half2 x6  = __ldg(&g_tab[qb.z + t]);
        __half2 x7  = __ldg(&g_tab[qb.w + t]);
        __half2 x8  = __ldg(&g_tab[qc.x + t]);
        __half2 x9  = __ldg(&g_tab[qc.y + t]);
        __half2 x10 = __ldg(&g_tab[qc.z + t]);
        __half2 x11 = __ldg(&g_tab[qc.w + t]);

        __half2 c0 = __hmax2(__hmax2(x0, x1), x2);
        __half2 c1 = __hmax2(__hmax2(x3, x4), x5);
        __half2 c2 = __hmax2(__hmax2(x6, x7), x8);
        __half2 c3 = __hmax2(__hmax2(x9, x10), x11);
        m = __hmin2(m, __hmin2(__hmin2(c0, c1), __hmin2(c2, c3)));
    }

    // uint bit order == float order for non-negative floats
    atomicMin(&out[2 * t + 0], __float_as_uint(__low2float(m)));
    atomicMin(&out[2 * t + 1], __float_as_uint(__high2float(m)));
}

extern "C" void kernel_launch(void* const* d_in, const int* in_sizes, int n_in,
                              void* d_out, int out_size) {
    const float*        input   = (const float*)d_in[0];
    const unsigned int* idx_raw = (const unsigned int*)d_in[1];
    const unsigned int* neg_raw = (const unsigned int*)d_in[2];
    unsigned int*       out     = (unsigned int*)d_out;

    detect_k<<<1, 1>>>(idx_raw);
    pack_k<<<(NC * 3 + 255) / 256, 256>>>(idx_raw, neg_raw);
    build_k<<<(NV * (B / 2) + 255) / 256, 256>>>(input);
    init_k<<<1, B>>>(out);
    cnf_k<<<GRID_MAIN, 128>>>(out);
}

// round 7
// speedup vs baseline: 1.0238x; 1.0238x over previous
#include <cuda_runtime.h>
#include <cuda_fp16.h>
#include <cstdint>

#define NV 10000
#define NC 100000
#define B  256
#define NGROUPS (NC / 4)           // 25000, exact
#define GRID_MAIN 1776             // 148 SMs * 12 blocks
#define GRID_PREP 2048

// Dual table: row 2v = x, row 2v+1 = 1-x, each row 128 half2 (256 batch).
// 10.24 MB, L2-resident. Both variants rounded directly from fp32, so every
// literal value carries rel err <= 2^-11 regardless of negation.
__device__ __half2 g_tab[2 * NV * (B / 2)];
// Per literal: half2-offset of its table row: (2v+neg)*128. 1.2 MB.
__device__ unsigned int g_off[NC * 3];

// Fused prologue: detect index dtype (per-block, redundant), pack literal
// offsets, build the fp16 dual table, init d_out to +inf. One kernel node.
__global__ void __launch_bounds__(256)
prep_k(const float* __restrict__ input,
       const unsigned int* __restrict__ idx_raw,
       const unsigned int* __restrict__ neg_raw,
       unsigned int* __restrict__ out) {
    __shared__ int s_is64;
    const int tid = threadIdx.x;

    // dtype probe: int64 data (small non-negative) -> odd 32-bit words all 0;
    // int32 data -> odd words are random indices, all-zero ~impossible.
    if (tid < 32) {
        unsigned int acc = 0;
        #pragma unroll
        for (int k = 0; k < 4; ++k) acc |= idx_raw[2 * (tid + 32 * k) + 1];
        acc = __reduce_or_sync(0xFFFFFFFFu, acc);
        if (tid == 0) s_is64 = (acc == 0) ? 1 : 0;
    }
    __syncthreads();
    const int stride = s_is64 ? 2 : 1;

    const int gtid = blockIdx.x * 256 + tid;
    const int gsz  = GRID_PREP * 256;

    // init output (poisoned 0xAA by harness every replay)
    if (gtid < B) out[gtid] = 0x7F800000u;   // +inf bit pattern

    // pack literal offsets
    for (int i = gtid; i < NC * 3; i += gsz) {
        unsigned int v = idx_raw[i * stride];
        unsigned int n = neg_raw[i * stride] & 1u;
        if (v >= NV) v = NV - 1;              // defensive clamp: no OOB ever
        g_off[i] = v * 256u + n * 128u;
    }

    // build dual table; 1-x computed in fp32 (exact), rounded once to fp16
    for (int i = gtid; i < NV * (B / 2); i += gsz) {
        int v = i >> 7;
        int j = i & 127;
        float2 x = ((const float2*)input)[i];
        g_tab[v * 256 + j]       = __floats2half2_rn(x.x, x.y);
        g_tab[v * 256 + 128 + j] = __floats2half2_rn(1.0f - x.x, 1.0f - x.y);
    }
}

// 128 threads/block, 12 blocks/SM. Thread t owns batch elems 2t,2t+1 (one
// half2 per gather -> each warp reads one full 128B line of a row).
// Grid-stride over 4-clause groups: 3x uint4 index loads + 12 LDG.32 gathers
// in flight, then pure hmax2/hmin2 (exact selects, no extra rounding).
__global__ void __launch_bounds__(128, 12)
cnf_k(unsigned int* __restrict__ out) {
    const int t = threadIdx.x;
    __half2 m = __halves2half2(__ushort_as_half(0x7C00), __ushort_as_half(0x7C00)); // +inf

    for (int g = blockIdx.x; g < NGROUPS; g += GRID_MAIN) {
        const uint4* q = (const uint4*)(g_off + g * 12);   // 48B-aligned
        uint4 qa = __ldg(&q[0]);
        uint4 qb = __ldg(&q[1]);
        uint4 qc = __ldg(&q[2]);

        __half2 x0  = __ldg(&g_tab[qa.x + t]);
        __half2 x1  = __ldg(&g_tab[qa.y + t]);
        __half2 x2  = __ldg(&g_tab[qa.z + t]);
        __half2 x3  = __ldg(&g_tab[qa.w + t]);
        __half2 x4  = __ldg(&g_tab[qb.x + t]);
        __half2 x5  = __ldg(&g_tab[qb.y + t]);
        __half2 x6  = __ldg(&g_tab[qb.z + t]);
        __half2 x7  = __ldg(&g_tab[qb.w + t]);
        __half2 x8  = __ldg(&g_tab[qc.x + t]);
        __half2 x9  = __ldg(&g_tab[qc.y + t]);
        __half2 x10 = __ldg(&g_tab[qc.z + t]);
        __half2 x11 = __ldg(&g_tab[qc.w + t]);

        __half2 c0 = __hmax2(__hmax2(x0, x1), x2);
        __half2 c1 = __hmax2(__hmax2(x3, x4), x5);
        __half2 c2 = __hmax2(__hmax2(x6, x7), x8);
        __half2 c3 = __hmax2(__hmax2(x9, x10), x11);
        m = __hmin2(m, __hmin2(__hmin2(c0, c1), __hmin2(c2, c3)));
    }

    // uint bit order == float order for non-negative floats
    atomicMin(&out[2 * t + 0], __float_as_uint(__low2float(m)));
    atomicMin(&out[2 * t + 1], __float_as_uint(__high2float(m)));
}

extern "C" void kernel_launch(void* const* d_in, const int* in_sizes, int n_in,
                              void* d_out, int out_size) {
    const float*        input   = (const float*)d_in[0];
    const unsigned int* idx_raw = (const unsigned int*)d_in[1];
    const unsigned int* neg_raw = (const unsigned int*)d_in[2];
    unsigned int*       out     = (unsigned int*)d_out;

    prep_k<<<GRID_PREP, 256>>>(input, idx_raw, neg_raw, out);
    cnf_k<<<GRID_MAIN, 128>>>(out);
}

// round 8
// speedup vs baseline: 1.3659x; 1.3341x over previous
#include <cuda_runtime.h>
#include <cuda_fp16.h>
#include <cstdint>

#define NV 10000
#define NC 100000
#define B  256
#define NGROUPS8 (NC / 8)          // 12500, exact
#define GRID_MAIN 1184             // 148 SMs * 8 blocks
#define GRID_PREP 2048

// Dual table: row 2v = x, row 2v+1 = 1-x, each row 128 half2 (256 batch).
// 10.24 MB, L2-resident. Both variants rounded directly from fp32, so every
// literal value carries rel err <= 2^-11 regardless of negation.
__device__ __half2 g_tab[2 * NV * (B / 2)];
// Per literal: half2-offset of its table row: (2v+neg)*128. 1.2 MB.
__device__ unsigned int g_off[NC * 3];

// Fused prologue: detect index dtype, pack literal offsets, build fp16 dual
// table, init d_out. One kernel node.
__global__ void __launch_bounds__(256)
prep_k(const float* __restrict__ input,
       const unsigned int* __restrict__ idx_raw,
       const unsigned int* __restrict__ neg_raw,
       unsigned int* __restrict__ out) {
    __shared__ int s_is64;
    const int tid = threadIdx.x;

    // dtype probe: int64 data (small non-negative) -> odd 32-bit words all 0;
    // int32 data -> odd words are random indices, all-zero ~impossible.
    if (tid < 32) {
        unsigned int acc = 0;
        #pragma unroll
        for (int k = 0; k < 4; ++k) acc |= idx_raw[2 * (tid + 32 * k) + 1];
        acc = __reduce_or_sync(0xFFFFFFFFu, acc);
        if (tid == 0) s_is64 = (acc == 0) ? 1 : 0;
    }
    __syncthreads();
    const int stride = s_is64 ? 2 : 1;

    const int gtid = blockIdx.x * 256 + tid;
    const int gsz  = GRID_PREP * 256;

    // init output (poisoned 0xAA by harness every replay)
    if (gtid < B) out[gtid] = 0x7F800000u;   // +inf bit pattern

    // pack literal offsets
    for (int i = gtid; i < NC * 3; i += gsz) {
        unsigned int v = idx_raw[i * stride];
        unsigned int n = neg_raw[i * stride] & 1u;
        if (v >= NV) v = NV - 1;              // defensive clamp: no OOB ever
        g_off[i] = v * 256u + n * 128u;
    }

    // build dual table; 1-x computed in fp32 (exact), rounded once to fp16
    for (int i = gtid; i < NV * (B / 2); i += gsz) {
        int v = i >> 7;
        int j = i & 127;
        float2 x = ((const float2*)input)[i];
        g_tab[v * 256 + j]       = __floats2half2_rn(x.x, x.y);
        g_tab[v * 256 + 128 + j] = __floats2half2_rn(1.0f - x.x, 1.0f - x.y);
    }
}

// 128 threads/block, 8 blocks/SM (64-reg budget: proven in R5 to be what lets
// ptxas keep the gather batch in flight). Thread t owns batch elems 2t,2t+1.
// 8 clauses per iteration: 6x uint4 index loads + 24 LDG.32 gathers issued
// before any consumption, then pure hmax2/hmin2 (exact selects).
__global__ void __launch_bounds__(128, 8)
cnf_k(unsigned int* __restrict__ out) {
    const int t = threadIdx.x;
    __half2 m = __halves2half2(__ushort_as_half(0x7C00), __ushort_as_half(0x7C00)); // +inf

    for (int g = blockIdx.x; g < NGROUPS8; g += GRID_MAIN) {
        const uint4* q = (const uint4*)(g_off + g * 24);   // 96B-aligned
        uint4 q0 = __ldg(&q[0]);
        uint4 q1 = __ldg(&q[1]);
        uint4 q2 = __ldg(&q[2]);
        uint4 q3 = __ldg(&q[3]);
        uint4 q4 = __ldg(&q[4]);
        uint4 q5 = __ldg(&q[5]);

        __half2 x0  = __ldg(&g_tab[q0.x + t]);
        __half2 x1  = __ldg(&g_tab[q0.y + t]);
        __half2 x2  = __ldg(&g_tab[q0.z + t]);
        __half2 x3  = __ldg(&g_tab[q0.w + t]);
        __half2 x4  = __ldg(&g_tab[q1.x + t]);
        __half2 x5  = __ldg(&g_tab[q1.y + t]);
        __half2 x6  = __ldg(&g_tab[q1.z + t]);
        __half2 x7  = __ldg(&g_tab[q1.w + t]);
        __half2 x8  = __ldg(&g_tab[q2.x + t]);
        __half2 x9  = __ldg(&g_tab[q2.y + t]);
        __half2 x10 = __ldg(&g_tab[q2.z + t]);
        __half2 x11 = __ldg(&g_tab[q2.w + t]);
        __half2 x12 = __ldg(&g_tab[q3.x + t]);
        __half2 x13 = __ldg(&g_tab[q3.y + t]);
        __half2 x14 = __ldg(&g_tab[q3.z + t]);
        __half2 x15 = __ldg(&g_tab[q3.w + t]);
        __half2 x16 = __ldg(&g_tab[q4.x + t]);
        __half2 x17 = __ldg(&g_tab[q4.y + t]);
        __half2 x18 = __ldg(&g_tab[q4.z + t]);
        __half2 x19 = __ldg(&g_tab[q4.w + t]);
        __half2 x20 = __ldg(&g_tab[q5.x + t]);
        __half2 x21 = __ldg(&g_tab[q5.y + t]);
        __half2 x22 = __ldg(&g_tab[q5.z + t]);
        __half2 x23 = __ldg(&g_tab[q5.w + t]);

        __half2 c0 = __hmax2(__hmax2(x0,  x1),  x2);
        __half2 c1 = __hmax2(__hmax2(x3,  x4),  x5);
        __half2 c2 = __hmax2(__hmax2(x6,  x7),  x8);
        __half2 c3 = __hmax2(__hmax2(x9,  x10), x11);
        __half2 c4 = __hmax2(__hmax2(x12, x13), x14);
        __half2 c5 = __hmax2(__hmax2(x15, x16), x17);
        __half2 c6 = __hmax2(__hmax2(x18, x19), x20);
        __half2 c7 = __hmax2(__hmax2(x21, x22), x23);

        __half2 l0 = __hmin2(__hmin2(c0, c1), __hmin2(c2, c3));
        __half2 l1 = __hmin2(__hmin2(c4, c5), __hmin2(c6, c7));
        m = __hmin2(m, __hmin2(l0, l1));
    }

    // uint bit order == float order for non-negative floats
    atomicMin(&out[2 * t + 0], __float_as_uint(__low2float(m)));
    atomicMin(&out[2 * t + 1], __float_as_uint(__high2float(m)));
}

extern "C" void kernel_launch(void* const* d_in, const int* in_sizes, int n_in,
                              void* d_out, int out_size) {
    const float*        input   = (const float*)d_in[0];
    const unsigned int* idx_raw = (const unsigned int*)d_in[1];
    const unsigned int* neg_raw = (const unsigned int*)d_in[2];
    unsigned int*       out     = (unsigned int*)d_out;

    prep_k<<<GRID_PREP, 256>>>(input, idx_raw, neg_raw, out);
    cnf_k<<<GRID_MAIN, 128>>>(out);
}